// round 1
// baseline (speedup 1.0000x reference)
#include <cuda_runtime.h>
#include <cuda_bf16.h>

// Problem constants (match reference exactly)
#define NN      50000
#define EE      800000
#define ET      850000   // EE + NN self loops
#define HID     128
#define HEADS   4
#define DH      32
#define NB      64
#define LAYERS  3
#define LN_EPS  1e-5f
#define NEG_SLOPE 0.2f

// ---------------- device scratch (static; no allocs allowed) ----------------
__device__ float g_h[NN * HID];
__device__ float g_tmp[NN * HID];
__device__ float g_as[NN * HEADS];
__device__ float g_ad[NN * HEADS];
__device__ int   g_deg[NN];
__device__ int   g_off[NN + 1];
__device__ int   g_cur[NN];
__device__ int   g_csr_src[ET];
__device__ float g_pooled[NB * HID];
__device__ float g_cnt[NB];

// ---------------- helpers ----------------
__device__ __forceinline__ float warpSum(float v) {
#pragma unroll
    for (int o = 16; o > 0; o >>= 1) v += __shfl_xor_sync(0xffffffffu, v, o);
    return v;
}
__device__ __forceinline__ float warpMax(float v) {
#pragma unroll
    for (int o = 16; o > 0; o >>= 1) v = fmaxf(v, __shfl_xor_sync(0xffffffffu, v, o));
    return v;
}
__device__ __forceinline__ float lrelu(float x) {
    return x > 0.f ? x : NEG_SLOPE * x;
}
__device__ __forceinline__ float silu(float x) {
    return x / (1.f + __expf(-x));
}

// ---------------- CSR build ----------------
__global__ void zero_deg_kernel(int* deg) {
    int i = blockIdx.x * blockDim.x + threadIdx.x;
    if (i < NN) deg[i] = 0;
}

__global__ void count_deg_kernel(const int* __restrict__ ei, int* __restrict__ deg) {
    int i = blockIdx.x * blockDim.x + threadIdx.x;
    if (i >= ET) return;
    int dst = (i < EE) ? ei[EE + i] : (i - EE);
    atomicAdd(&deg[dst], 1);
}

__global__ void scan_kernel(const int* __restrict__ deg, int* __restrict__ off) {
    __shared__ int wsum[32];
    __shared__ int carry;
    int tid = threadIdx.x, lane = tid & 31, w = tid >> 5;
    if (tid == 0) carry = 0;
    __syncthreads();
    for (int base = 0; base < NN; base += 1024) {
        int i = base + tid;
        int v = (i < NN) ? deg[i] : 0;
        int x = v;
#pragma unroll
        for (int o = 1; o < 32; o <<= 1) {
            int t = __shfl_up_sync(0xffffffffu, x, o);
            if (lane >= o) x += t;
        }
        if (lane == 31) wsum[w] = x;
        __syncthreads();
        if (w == 0) {
            int s = wsum[lane];
#pragma unroll
            for (int o = 1; o < 32; o <<= 1) {
                int t = __shfl_up_sync(0xffffffffu, s, o);
                if (lane >= o) s += t;
            }
            wsum[lane] = s;
        }
        __syncthreads();
        int excl = x - v + (w ? wsum[w - 1] : 0) + carry;
        if (i < NN) off[i] = excl;
        __syncthreads();
        if (tid == 0) carry += wsum[31];
        __syncthreads();
    }
    if (threadIdx.x == 0) off[NN] = carry;
}

__global__ void copy_cursor_kernel(const int* __restrict__ off, int* __restrict__ cur) {
    int i = blockIdx.x * blockDim.x + threadIdx.x;
    if (i < NN) cur[i] = off[i];
}

__global__ void scatter_kernel(const int* __restrict__ ei, int* __restrict__ cur,
                               int* __restrict__ csr_src) {
    int i = blockIdx.x * blockDim.x + threadIdx.x;
    if (i >= ET) return;
    int src, dst;
    if (i < EE) { src = ei[i]; dst = ei[EE + i]; }
    else        { src = i - EE; dst = i - EE; }
    int pos = atomicAdd(&cur[dst], 1);
    csr_src[pos] = src;
}

// ---------------- SGEMM: C[M,128] = A[M,128] @ W[128,128] ----------------
// BM=64, BN=128, BK=32, 256 threads, 8x4 micro-tile per thread.
__global__ void gemm128_kernel(const float* __restrict__ A, const float* __restrict__ W,
                               float* __restrict__ C, int M) {
    __shared__ float As[32][64];   // [k][m] transposed
    __shared__ float Bs[32][128];  // [k][n]
    const int tid  = threadIdx.x;
    const int tcol = tid & 31;   // 0..31 -> col base tcol*4
    const int trow = tid >> 5;   // 0..7  -> row base trow*8
    const int row0 = blockIdx.x * 64;

    float acc[8][4];
#pragma unroll
    for (int i = 0; i < 8; i++)
#pragma unroll
        for (int j = 0; j < 4; j++) acc[i][j] = 0.f;

    for (int k0 = 0; k0 < 128; k0 += 32) {
        // A tile: 64 rows x 32 k, 512 float4 slots, 2 per thread
#pragma unroll
        for (int t = 0; t < 2; t++) {
            int s  = tid + t * 256;
            int m  = s >> 3;
            int kk = (s & 7) << 2;
            int r  = row0 + m;
            float4 v = make_float4(0.f, 0.f, 0.f, 0.f);
            if (r < M) v = *(const float4*)(A + (long)r * 128 + k0 + kk);
            As[kk + 0][m] = v.x; As[kk + 1][m] = v.y;
            As[kk + 2][m] = v.z; As[kk + 3][m] = v.w;
        }
        // B tile: 32 k x 128 cols, 1024 float4 slots, 4 per thread
#pragma unroll
        for (int t = 0; t < 4; t++) {
            int s  = tid + t * 256;
            int kk = s >> 5;
            int c  = (s & 31) << 2;
            *(float4*)&Bs[kk][c] = *(const float4*)(W + (k0 + kk) * 128 + c);
        }
        __syncthreads();
#pragma unroll
        for (int kk = 0; kk < 32; kk++) {
            float4 A0 = *(const float4*)&As[kk][trow * 8];
            float4 A1 = *(const float4*)&As[kk][trow * 8 + 4];
            float4 B0 = *(const float4*)&Bs[kk][tcol * 4];
            float a[8] = {A0.x, A0.y, A0.z, A0.w, A1.x, A1.y, A1.z, A1.w};
            float b[4] = {B0.x, B0.y, B0.z, B0.w};
#pragma unroll
            for (int i = 0; i < 8; i++)
#pragma unroll
                for (int j = 0; j < 4; j++) acc[i][j] += a[i] * b[j];
        }
        __syncthreads();
    }
#pragma unroll
    for (int i = 0; i < 8; i++) {
        int r = row0 + trow * 8 + i;
        if (r < M) {
            float4 v = make_float4(acc[i][0], acc[i][1], acc[i][2], acc[i][3]);
            *(float4*)(C + (long)r * 128 + tcol * 4) = v;
        }
    }
}

// ---------------- encoder LN + SiLU (warp per node) ----------------
__global__ void ln_silu_kernel(const float* __restrict__ in, const float* __restrict__ bias,
                               const float* __restrict__ g, const float* __restrict__ be,
                               float* __restrict__ out) {
    int warp = (blockIdx.x * blockDim.x + threadIdx.x) >> 5;
    if (warp >= NN) return;
    int lane = threadIdx.x & 31;
    int col  = lane * 4;
    float4 v  = *(const float4*)(in + (long)warp * 128 + col);
    float4 b4 = *(const float4*)(bias + col);
    v.x += b4.x; v.y += b4.y; v.z += b4.z; v.w += b4.w;
    float mu = warpSum(v.x + v.y + v.z + v.w) * (1.f / 128.f);
    float dx = v.x - mu, dy = v.y - mu, dz = v.z - mu, dw = v.w - mu;
    float var = warpSum(dx * dx + dy * dy + dz * dz + dw * dw) * (1.f / 128.f);
    float r = rsqrtf(var + LN_EPS);
    float4 gv  = *(const float4*)(g + col);
    float4 bev = *(const float4*)(be + col);
    float y;
    y = dx * r * gv.x + bev.x; v.x = silu(y);
    y = dy * r * gv.y + bev.y; v.y = silu(y);
    y = dz * r * gv.z + bev.z; v.z = silu(y);
    y = dw * r * gv.w + bev.w; v.w = silu(y);
    *(float4*)(out + (long)warp * 128 + col) = v;
}

// ---------------- per-node attention logits ----------------
__global__ void attn_prep_kernel(const float* __restrict__ hh, const float* __restrict__ ws,
                                 const float* __restrict__ wd, float* __restrict__ a_s,
                                 float* __restrict__ a_d) {
    int idx = blockIdx.x * blockDim.x + threadIdx.x;
    if (idx >= NN * HEADS) return;
    int n = idx >> 2, hd = idx & 3;
    const float* row = hh + (long)n * 128 + hd * 32;
    const float* s1  = ws + hd * 32;
    const float* s2  = wd + hd * 32;
    float u = 0.f, t = 0.f;
#pragma unroll
    for (int d = 0; d < 32; d += 4) {
        float4 v  = *(const float4*)(row + d);
        float4 w1 = *(const float4*)(s1 + d);
        float4 w2 = *(const float4*)(s2 + d);
        u += v.x * w1.x + v.y * w1.y + v.z * w1.z + v.w * w1.w;
        t += v.x * w2.x + v.y * w2.y + v.z * w2.z + v.w * w2.w;
    }
    a_s[idx] = u;
    a_d[idx] = t;
}

// ---------------- GAT aggregate + LN + SiLU + residual (warp per dst node) --
__global__ void gat_aggregate_kernel(const float* __restrict__ hh, const float* __restrict__ a_s,
                                     const float* __restrict__ a_d, const int* __restrict__ off,
                                     const int* __restrict__ csr_src, const float* __restrict__ bg,
                                     const float* __restrict__ gg, const float* __restrict__ bgg,
                                     float* __restrict__ h) {
    int n = (blockIdx.x * blockDim.x + threadIdx.x) >> 5;
    if (n >= NN) return;
    int lane = threadIdx.x & 31;
    int beg = off[n], end = off[n + 1];

    float4 adv = *(const float4*)(a_d + n * 4);
    float m0 = -1e30f, m1 = -1e30f, m2 = -1e30f, m3 = -1e30f;
    // pass 1: per-head max over incoming edges
    for (int j = beg + lane; j < end; j += 32) {
        int s = csr_src[j];
        float4 asv = *(const float4*)(a_s + s * 4);
        m0 = fmaxf(m0, lrelu(asv.x + adv.x));
        m1 = fmaxf(m1, lrelu(asv.y + adv.y));
        m2 = fmaxf(m2, lrelu(asv.z + adv.z));
        m3 = fmaxf(m3, lrelu(asv.w + adv.w));
    }
    m0 = warpMax(m0); m1 = warpMax(m1); m2 = warpMax(m2); m3 = warpMax(m3);
    // pass 2: per-head sum of exp(e - m)
    float s0 = 0.f, s1 = 0.f, s2 = 0.f, s3 = 0.f;
    for (int j = beg + lane; j < end; j += 32) {
        int s = csr_src[j];
        float4 asv = *(const float4*)(a_s + s * 4);
        s0 += __expf(lrelu(asv.x + adv.x) - m0);
        s1 += __expf(lrelu(asv.y + adv.y) - m1);
        s2 += __expf(lrelu(asv.z + adv.z) - m2);
        s3 += __expf(lrelu(asv.w + adv.w) - m3);
    }
    s0 = warpSum(s0); s1 = warpSum(s1); s2 = warpSum(s2); s3 = warpSum(s3);

    int hd = lane >> 3;  // head owning this lane's 4 output dims
    float mh   = (hd == 0) ? m0 : (hd == 1) ? m1 : (hd == 2) ? m2 : m3;
    float adh  = (hd == 0) ? adv.x : (hd == 1) ? adv.y : (hd == 2) ? adv.z : adv.w;
    float invh = 1.f / ((hd == 0) ? s0 : (hd == 1) ? s1 : (hd == 2) ? s2 : s3);

    const int col = lane * 4;
    float4 acc = make_float4(0.f, 0.f, 0.f, 0.f);
    // pass 3: weighted accumulate of hh[src]
    for (int j = beg; j < end; j++) {
        int s = csr_src[j];
        float w = __expf(lrelu(a_s[s * 4 + hd] + adh) - mh) * invh;
        float4 v = *(const float4*)(hh + (long)s * 128 + col);
        acc.x += v.x * w; acc.y += v.y * w; acc.z += v.z * w; acc.w += v.w * w;
    }
    // + bg, LayerNorm, SiLU, + residual
    float4 bgv = *(const float4*)(bg + col);
    acc.x += bgv.x; acc.y += bgv.y; acc.z += bgv.z; acc.w += bgv.w;
    float mu = warpSum(acc.x + acc.y + acc.z + acc.w) * (1.f / 128.f);
    float dx = acc.x - mu, dy = acc.y - mu, dz = acc.z - mu, dw = acc.w - mu;
    float var = warpSum(dx * dx + dy * dy + dz * dz + dw * dw) * (1.f / 128.f);
    float r = rsqrtf(var + LN_EPS);
    float4 gv  = *(const float4*)(gg + col);
    float4 bv  = *(const float4*)(bgg + col);
    float4 old = *(const float4*)(h + (long)n * 128 + col);
    float y;
    y = dx * r * gv.x + bv.x; acc.x = silu(y) + old.x;
    y = dy * r * gv.y + bv.y; acc.y = silu(y) + old.y;
    y = dz * r * gv.z + bv.z; acc.z = silu(y) + old.z;
    y = dw * r * gv.w + bv.w; acc.w = silu(y) + old.w;
    *(float4*)(h + (long)n * 128 + col) = acc;
}

// ---------------- pooling ----------------
__global__ void zero_pool_kernel(float* pooled, float* cnt) {
    int i = blockIdx.x * blockDim.x + threadIdx.x;
    if (i < NB * HID) pooled[i] = 0.f;
    if (i < NB) cnt[i] = 0.f;
}

__global__ void pool_acc_kernel(const float* __restrict__ h, const int* __restrict__ batch,
                                float* __restrict__ pooled, float* __restrict__ cnt) {
    long idx = (long)blockIdx.x * blockDim.x + threadIdx.x;
    if (idx >= (long)NN * HID) return;
    int n = (int)(idx >> 7);
    int c = (int)(idx & 127);
    int b = batch[n];
    atomicAdd(&pooled[b * HID + c], h[idx]);
    if (c == 0) atomicAdd(&cnt[b], 1.f);
}

// ---------------- final projection + LN + SiLU ----------------
__global__ void final_kernel(const float* __restrict__ pooled, const float* __restrict__ cnt,
                             const float* __restrict__ Wp, const float* __restrict__ bp,
                             const float* __restrict__ gp, const float* __restrict__ bep,
                             float* __restrict__ out) {
    __shared__ float p[128];
    __shared__ float sh[4];
    int b = blockIdx.x, t = threadIdx.x;
    int lane = t & 31, w = t >> 5;
    float c = fmaxf(cnt[b], 1.f);
    p[t] = pooled[b * 128 + t] / c;
    __syncthreads();
    float s = bp[t];
#pragma unroll 8
    for (int k = 0; k < 128; k++) s += p[k] * Wp[k * 128 + t];
    // block LN (128 threads, 4 warps)
    float v = warpSum(s);
    if (lane == 0) sh[w] = v;
    __syncthreads();
    float mu = (sh[0] + sh[1] + sh[2] + sh[3]) * (1.f / 128.f);
    __syncthreads();
    float d = s - mu;
    v = warpSum(d * d);
    if (lane == 0) sh[w] = v;
    __syncthreads();
    float var = (sh[0] + sh[1] + sh[2] + sh[3]) * (1.f / 128.f);
    float r = rsqrtf(var + LN_EPS);
    float y = d * r * gp[t] + bep[t];
    out[b * 128 + t] = silu(y);
}

// ---------------- launch ----------------
extern "C" void kernel_launch(void* const* d_in, const int* in_sizes, int n_in,
                              void* d_out, int out_size) {
    const float* x       = (const float*)d_in[0];
    const int*   ei      = (const int*)d_in[1];
    const int*   batch   = (const int*)d_in[2];
    const float* W0      = (const float*)d_in[3];
    const float* b0      = (const float*)d_in[4];
    const float* g0      = (const float*)d_in[5];
    const float* be0     = (const float*)d_in[6];
    const float* Wg      = (const float*)d_in[7];
    const float* att_src = (const float*)d_in[8];
    const float* att_dst = (const float*)d_in[9];
    const float* bg      = (const float*)d_in[10];
    const float* gg      = (const float*)d_in[11];
    const float* bgg     = (const float*)d_in[12];
    const float* Wp      = (const float*)d_in[13];
    const float* bp      = (const float*)d_in[14];
    const float* gp      = (const float*)d_in[15];
    const float* bep     = (const float*)d_in[16];
    float* out = (float*)d_out;

    float *h, *tmp, *as_, *ad_, *pooled, *cnt;
    int *deg, *off, *cur, *csr;
    cudaGetSymbolAddress((void**)&h, g_h);
    cudaGetSymbolAddress((void**)&tmp, g_tmp);
    cudaGetSymbolAddress((void**)&as_, g_as);
    cudaGetSymbolAddress((void**)&ad_, g_ad);
    cudaGetSymbolAddress((void**)&deg, g_deg);
    cudaGetSymbolAddress((void**)&off, g_off);
    cudaGetSymbolAddress((void**)&cur, g_cur);
    cudaGetSymbolAddress((void**)&csr, g_csr_src);
    cudaGetSymbolAddress((void**)&pooled, g_pooled);
    cudaGetSymbolAddress((void**)&cnt, g_cnt);

    // --- CSR by dst (built once, reused by all 3 layers) ---
    zero_deg_kernel<<<(NN + 255) / 256, 256>>>(deg);
    count_deg_kernel<<<(ET + 255) / 256, 256>>>(ei, deg);
    scan_kernel<<<1, 1024>>>(deg, off);
    copy_cursor_kernel<<<(NN + 255) / 256, 256>>>(off, cur);
    scatter_kernel<<<(ET + 255) / 256, 256>>>(ei, cur, csr);

    // --- node encoder: h = silu(ln(x @ W0 + b0)) ---
    gemm128_kernel<<<(NN + 63) / 64, 256>>>(x, W0, tmp, NN);
    ln_silu_kernel<<<(NN * 32 + 255) / 256, 256>>>(tmp, b0, g0, be0, h);

    // --- 3 GAT layers ---
    for (int l = 0; l < LAYERS; l++) {
        gemm128_kernel<<<(NN + 63) / 64, 256>>>(h, Wg + (long)l * 128 * 128, tmp, NN);
        attn_prep_kernel<<<(NN * HEADS + 255) / 256, 256>>>(
            tmp, att_src + l * 128, att_dst + l * 128, as_, ad_);
        gat_aggregate_kernel<<<(NN * 32 + 255) / 256, 256>>>(
            tmp, as_, ad_, off, csr, bg + l * 128, gg + l * 128, bgg + l * 128, h);
    }

    // --- global mean pool + output projection ---
    zero_pool_kernel<<<(NB * HID + 255) / 256, 256>>>(pooled, cnt);
    pool_acc_kernel<<<(int)(((long)NN * HID + 255) / 256), 256>>>(h, batch, pooled, cnt);
    final_kernel<<<NB, 128>>>(pooled, cnt, Wp, bp, gp, bep, out);
}